// round 9
// baseline (speedup 1.0000x reference)
#include <cuda_runtime.h>

#define HDIM 256
#define MAX_E 200000
#define MAX_N 50000
#define MAX_BT (MAX_E * 8)

// ---------------- static scratch ----------------
__device__ float g_msg_input[MAX_E * HDIM];
__device__ float g_msgA[MAX_E * HDIM];
__device__ float g_msgB[MAX_E * HDIM];
__device__ float g_node_alpha[MAX_N * HDIM];
__device__ float g_ns[MAX_N * HDIM];
__device__ float g_m[MAX_N * HDIM];
__device__ float g_h[MAX_N * HDIM];
__device__ unsigned g_Wh[HDIM * HDIM];    // W_h pre-converted to tf32
__device__ int   g_cnt[MAX_E];
__device__ int   g_node_ptr[MAX_N + 1];
__device__ int   g_in_idx[MAX_E];
__device__ int   g_bt_ptr[MAX_E + 1];
__device__ int   g_bt_idx[MAX_BT];

// ---------------- helpers ----------------
__device__ __forceinline__ unsigned f2tf(float x) {
    unsigned u; asm("cvt.rna.tf32.f32 %0, %1;" : "=r"(u) : "f"(x)); return u;
}
__device__ __forceinline__ void mma_tf32(float* c, const unsigned* a, const unsigned* b) {
    asm volatile(
        "mma.sync.aligned.m16n8k8.row.col.f32.tf32.tf32.f32 "
        "{%0,%1,%2,%3}, {%4,%5,%6,%7}, {%8,%9}, {%0,%1,%2,%3};\n"
        : "+f"(c[0]), "+f"(c[1]), "+f"(c[2]), "+f"(c[3])
        : "r"(a[0]), "r"(a[1]), "r"(a[2]), "r"(a[3]), "r"(b[0]), "r"(b[1]));
}

// ---------------- CSR builds ----------------
__global__ void k_zero_cnt(int n) {
    int i = blockIdx.x * blockDim.x + threadIdx.x;
    if (i < n) g_cnt[i] = 0;
}
__global__ void k_count(const int* __restrict__ edst, int E) {
    int e = blockIdx.x * blockDim.x + threadIdx.x;
    if (e < E) atomicAdd(&g_cnt[edst[e]], 1);
}
__global__ void k_scan(int* __restrict__ ptr, int n, int rezero) {
    __shared__ int sh[1024];
    __shared__ int carry;
    int tid = threadIdx.x;
    if (tid == 0) { carry = 0; ptr[0] = 0; }
    __syncthreads();
    for (int base = 0; base < n; base += 1024) {
        int i = base + tid;
        int v = (i < n) ? g_cnt[i] : 0;
        sh[tid] = v; __syncthreads();
        for (int off = 1; off < 1024; off <<= 1) {
            int add = (tid >= off) ? sh[tid - off] : 0;
            __syncthreads();
            sh[tid] += add; __syncthreads();
        }
        if (i < n) { ptr[i + 1] = carry + sh[tid]; if (rezero) g_cnt[i] = 0; }
        __syncthreads();
        if (tid == 0) carry += sh[1023];
        __syncthreads();
    }
}
__global__ void k_place(const int* __restrict__ edst, int E) {
    int e = blockIdx.x * blockDim.x + threadIdx.x;
    if (e >= E) return;
    int v = edst[e];
    int pos = atomicAdd(&g_cnt[v], 1);
    g_in_idx[g_node_ptr[v] + pos] = e;
}
__global__ void k_bt_count(const int* __restrict__ esrc, const int* __restrict__ edst, int E) {
    int e = blockIdx.x * blockDim.x + threadIdx.x;
    if (e >= E) return;
    int sv = esrc[e], dv = edst[e];
    int cnt = 0;
    for (int j = g_node_ptr[sv]; j < g_node_ptr[sv + 1]; j++)
        if (esrc[g_in_idx[j]] == dv) cnt++;
    g_cnt[e] = cnt;
}
__global__ void k_bt_fill(const int* __restrict__ esrc, const int* __restrict__ edst, int E) {
    int e = blockIdx.x * blockDim.x + threadIdx.x;
    if (e >= E) return;
    int sv = esrc[e], dv = edst[e];
    int k = g_bt_ptr[e];
    for (int j = g_node_ptr[sv]; j < g_node_ptr[sv + 1]; j++) {
        int e2 = g_in_idx[j];
        if (esrc[e2] == dv && k < MAX_BT) g_bt_idx[k++] = e2;
    }
}

// ---------------- misc ----------------
__global__ void k_zero_alpha(int n) {
    int i = blockIdx.x * blockDim.x + threadIdx.x;
    if (i < n) g_node_alpha[i] = 0.f;
}
__global__ void k_scatter_alpha(const float* __restrict__ tree_m,
                                const int* __restrict__ tgt,
                                const int* __restrict__ teid, int K) {
    int i = blockIdx.x * blockDim.x + threadIdx.x;
    int k = i >> 8, h = i & 255;
    if (k >= K) return;
    atomicAdd(&g_node_alpha[tgt[k] * HDIM + h], tree_m[teid[k] * HDIM + h]);
}
__global__ void k_convW(const float* __restrict__ W_h) {
    int i = blockIdx.x * blockDim.x + threadIdx.x;
    if (i < HDIM * HDIM) g_Wh[i] = f2tf(W_h[i]);
}

// ---------------- per-node sum: out[v] = alpha[v] + sum msg_in[in(v)] ----------------
__global__ __launch_bounds__(256)
void k_nodesum(int buf, int to_m, int N) {
    const float* __restrict__ msg_in = buf ? g_msgB : g_msgA;
    float* __restrict__ outp = to_m ? g_m : g_ns;
    int v = blockIdx.x * 4 + (threadIdx.x >> 6);
    if (v >= N) return;
    int t4 = (threadIdx.x & 63) * 4;
    float4 acc = *(const float4*)&g_node_alpha[(long)v * HDIM + t4];
    int s = g_node_ptr[v], en = g_node_ptr[v + 1];
    int i = s;
    for (; i + 4 <= en; i += 4) {
        int i0 = g_in_idx[i], i1 = g_in_idx[i + 1], i2 = g_in_idx[i + 2], i3 = g_in_idx[i + 3];
        float4 v0 = *(const float4*)&msg_in[(long)i0 * HDIM + t4];
        float4 v1 = *(const float4*)&msg_in[(long)i1 * HDIM + t4];
        float4 v2 = *(const float4*)&msg_in[(long)i2 * HDIM + t4];
        float4 v3 = *(const float4*)&msg_in[(long)i3 * HDIM + t4];
        acc.x += v0.x + v1.x + v2.x + v3.x;
        acc.y += v0.y + v1.y + v2.y + v3.y;
        acc.z += v0.z + v1.z + v2.z + v3.z;
        acc.w += v0.w + v1.w + v2.w + v3.w;
    }
    for (; i < en; i++) {
        float4 vv = *(const float4*)&msg_in[(long)g_in_idx[i] * HDIM + t4];
        acc.x += vv.x; acc.y += vv.y; acc.z += vv.z; acc.w += vv.w;
    }
    *(float4*)&outp[(long)v * HDIM + t4] = acc;
}

// ---------------- fused BP: BM=128 x BN=256, 512 threads, double-buffered B ----------------
#define AS(r, c) As[(r) * 260 + (c)]
#define BS(b, r, c) Bs[(b) * (16 * 264) + (r) * 264 + (c)]
#define BP_SMEM ((128 * 260 + 2 * 16 * 264) * 4)

__global__ __launch_bounds__(512, 1)
void k_bp_fused(const int* __restrict__ esrc, int E, int buf) {
    const float* __restrict__ msg_in  = buf ? g_msgB : g_msgA;
    float*       __restrict__ msg_out = buf ? g_msgA : g_msgB;

    extern __shared__ unsigned smem_u[];
    unsigned* As = smem_u;              // [128][260]
    unsigned* Bs = smem_u + 128 * 260;  // [2][16][264]

    int tid = threadIdx.x;
    int lane = tid & 31, wid = tid >> 5;          // 16 warps
    int gg = lane >> 2, tig = lane & 3;
    int wm = (wid & 3) * 32, wn = (wid >> 2) * 64;
    long row0 = (long)blockIdx.x * 128;

    // ---- phase 1: A[e] = ns[src[e]] - (rare) backtrack rows ----
    {
        int grp = tid >> 6;            // 8 groups of 64 threads
        int t4  = (tid & 63) * 4;
#pragma unroll
        for (int ib = 0; ib < 16; ib += 4) {
            float4 v[4];
            int rrs[4];
#pragma unroll
            for (int u = 0; u < 4; u++) {
                int rr = grp + (ib + u) * 8;
                rrs[u] = rr;
                long e = row0 + rr;
                if (e < E) {
                    int sv = esrc[e];
                    v[u] = *(const float4*)&g_ns[(long)sv * HDIM + t4];
                } else {
                    v[u] = make_float4(0, 0, 0, 0);
                }
            }
#pragma unroll
            for (int u = 0; u < 4; u++) {
                long e = row0 + rrs[u];
                if (e < E) {
                    int b0 = g_bt_ptr[e], b1 = g_bt_ptr[e + 1];
                    for (int j = b0; j < b1; j++) {
                        float4 w = *(const float4*)&msg_in[(long)g_bt_idx[j] * HDIM + t4];
                        v[u].x -= w.x; v[u].y -= w.y; v[u].z -= w.z; v[u].w -= w.w;
                    }
                }
                uint4 st;
                st.x = f2tf(v[u].x); st.y = f2tf(v[u].y); st.z = f2tf(v[u].z); st.w = f2tf(v[u].w);
                *(uint4*)&AS(rrs[u], t4) = st;
            }
        }
    }

    float c[2][8][4];
#pragma unroll
    for (int mt = 0; mt < 2; mt++)
#pragma unroll
        for (int nt = 0; nt < 8; nt++)
#pragma unroll
            for (int r = 0; r < 4; r++) c[mt][nt][r] = 0.f;

    // preload B tile 0 (16x256 tf32 = 1024 uint4, 2 per thread)
    {
#pragma unroll
        for (int u = 0; u < 2; u++) {
            int idx = tid + u * 512;
            int krow = idx >> 6, cc4 = idx & 63;
            *(uint4*)&BS(0, krow, cc4 * 4) = *(const uint4*)&g_Wh[krow * 256 + cc4 * 4];
        }
    }
    __syncthreads();

    // ---- phase 2: GEMM over 16 k-tiles, double-buffered B, 1 BAR/tile ----
    for (int kt = 0; kt < 16; kt++) {
        int cbuf = kt & 1, nbuf = cbuf ^ 1;
        if (kt < 15) {
            int k0 = (kt + 1) * 16;
#pragma unroll
            for (int u = 0; u < 2; u++) {
                int idx = tid + u * 512;
                int krow = idx >> 6, cc4 = idx & 63;
                *(uint4*)&BS(nbuf, krow, cc4 * 4) = *(const uint4*)&g_Wh[(k0 + krow) * 256 + cc4 * 4];
            }
        }
#pragma unroll
        for (int ks = 0; ks < 16; ks += 8) {
            unsigned a[2][4], b[8][2];
            int kbase = kt * 16 + ks;
#pragma unroll
            for (int mt = 0; mt < 2; mt++) {
                int m0 = wm + mt * 16 + gg;
                a[mt][0] = AS(m0,     kbase + tig);
                a[mt][1] = AS(m0 + 8, kbase + tig);
                a[mt][2] = AS(m0,     kbase + tig + 4);
                a[mt][3] = AS(m0 + 8, kbase + tig + 4);
            }
#pragma unroll
            for (int nt = 0; nt < 8; nt++) {
                int n0 = wn + nt * 8 + gg;
                b[nt][0] = BS(cbuf, ks + tig,     n0);
                b[nt][1] = BS(cbuf, ks + tig + 4, n0);
            }
#pragma unroll
            for (int mt = 0; mt < 2; mt++)
#pragma unroll
                for (int nt = 0; nt < 8; nt++)
                    mma_tf32(c[mt][nt], a[mt], b[nt]);
        }
        __syncthreads();
    }

    // ---- epilogue: msg_out = relu(msg_input + acc) ----
#pragma unroll
    for (int mt = 0; mt < 2; mt++) {
#pragma unroll
        for (int nt = 0; nt < 8; nt++) {
            int col = wn + nt * 8 + tig * 2;
            long r0 = row0 + wm + mt * 16 + gg;
            if (r0 < E) {
                float2 mi = *(const float2*)&g_msg_input[r0 * 256 + col];
                float2 o;
                o.x = fmaxf(mi.x + c[mt][nt][0], 0.f);
                o.y = fmaxf(mi.y + c[mt][nt][1], 0.f);
                *(float2*)&msg_out[r0 * 256 + col] = o;
            }
            long r1 = r0 + 8;
            if (r1 < E) {
                float2 mi = *(const float2*)&g_msg_input[r1 * 256 + col];
                float2 o;
                o.x = fmaxf(mi.x + c[mt][nt][2], 0.f);
                o.y = fmaxf(mi.y + c[mt][nt][3], 0.f);
                *(float2*)&msg_out[r1 * 256 + col] = o;
            }
        }
    }
}

// ---------------- tf32 GEMM kernels (edge input, output) ----------------
#define APAD 20
#define BPAD 264

__global__ __launch_bounds__(256)
void k_edge_tf32(const float* __restrict__ x_nodes, const float* __restrict__ x_edges,
                 const float* __restrict__ W_i, const int* __restrict__ esrc, int E) {
    __shared__ unsigned As[2][64][APAD];
    __shared__ unsigned Bs[2][16][BPAD];
    int tid = threadIdx.x;
    int lane = tid & 31, wid = tid >> 5;
    int gg = lane >> 2, tig = lane & 3;
    int wm = (wid & 1) * 32, wn = (wid >> 1) * 64;
    long row0 = (long)blockIdx.x * 64;

    float c[2][8][4];
#pragma unroll
    for (int mt = 0; mt < 2; mt++)
#pragma unroll
        for (int nt = 0; nt < 8; nt++)
#pragma unroll
            for (int r = 0; r < 4; r++) c[mt][nt][r] = 0.f;

    const int NT = 3;
    {
#pragma unroll
        for (int u = 0; u < 4; u++) {
            int i = tid + u * 256;
            int row = i >> 4, kk = i & 15;
            long r = row0 + row;
            float v = 0.f;
            if (r < E && kk < 40)
                v = (kk < 35) ? x_nodes[(long)esrc[r] * 35 + kk] : x_edges[r * 5 + (kk - 35)];
            As[0][row][kk] = f2tf(v);
        }
#pragma unroll
        for (int u = 0; u < 4; u++) {
            int ff = tid + u * 256, krow = ff >> 6, cc = ff & 63;
            float4 bvv = make_float4(0, 0, 0, 0);
            if (krow < 40) bvv = *(const float4*)&W_i[krow * 256 + cc * 4];
            unsigned* q = &Bs[0][krow][cc * 4];
            q[0] = f2tf(bvv.x); q[1] = f2tf(bvv.y); q[2] = f2tf(bvv.z); q[3] = f2tf(bvv.w);
        }
    }
    __syncthreads();

    for (int kt = 0; kt < NT; kt++) {
        int cbuf = kt & 1, nbuf = cbuf ^ 1;
        float avs[4]; float4 bv[4];
        if (kt < NT - 1) {
            int k0 = (kt + 1) * 16;
#pragma unroll
            for (int u = 0; u < 4; u++) {
                int i = tid + u * 256;
                int row = i >> 4, kk = i & 15;
                long r = row0 + row; int gk = k0 + kk;
                float v = 0.f;
                if (r < E && gk < 40)
                    v = (gk < 35) ? x_nodes[(long)esrc[r] * 35 + gk] : x_edges[r * 5 + (gk - 35)];
                avs[u] = v;
            }
#pragma unroll
            for (int u = 0; u < 4; u++) {
                int ff = tid + u * 256, krow = ff >> 6, cc = ff & 63;
                int gk = k0 + krow;
                bv[u] = make_float4(0, 0, 0, 0);
                if (gk < 40) bv[u] = *(const float4*)&W_i[gk * 256 + cc * 4];
            }
        }
#pragma unroll
        for (int ks = 0; ks < 16; ks += 8) {
            unsigned a[2][4], b[8][2];
#pragma unroll
            for (int mt = 0; mt < 2; mt++) {
                int m0 = wm + mt * 16 + gg;
                a[mt][0] = As[cbuf][m0][ks + tig];
                a[mt][1] = As[cbuf][m0 + 8][ks + tig];
                a[mt][2] = As[cbuf][m0][ks + tig + 4];
                a[mt][3] = As[cbuf][m0 + 8][ks + tig + 4];
            }
#pragma unroll
            for (int nt = 0; nt < 8; nt++) {
                int n0 = wn + nt * 8 + gg;
                b[nt][0] = Bs[cbuf][ks + tig][n0];
                b[nt][1] = Bs[cbuf][ks + tig + 4][n0];
            }
#pragma unroll
            for (int mt = 0; mt < 2; mt++)
#pragma unroll
                for (int nt = 0; nt < 8; nt++)
                    mma_tf32(c[mt][nt], a[mt], b[nt]);
        }
        if (kt < NT - 1) {
#pragma unroll
            for (int u = 0; u < 4; u++) {
                int i = tid + u * 256;
                int row = i >> 4, kk = i & 15;
                As[nbuf][row][kk] = f2tf(avs[u]);
            }
#pragma unroll
            for (int u = 0; u < 4; u++) {
                int ff = tid + u * 256, krow = ff >> 6, cc = ff & 63;
                unsigned* q = &Bs[nbuf][krow][cc * 4];
                q[0] = f2tf(bv[u].x); q[1] = f2tf(bv[u].y); q[2] = f2tf(bv[u].z); q[3] = f2tf(bv[u].w);
            }
        }
        __syncthreads();
    }

#pragma unroll
    for (int mt = 0; mt < 2; mt++) {
#pragma unroll
        for (int nt = 0; nt < 8; nt++) {
            int col = wn + nt * 8 + tig * 2;
            long r0 = row0 + wm + mt * 16 + gg;
            if (r0 < E) {
                float2 v = make_float2(c[mt][nt][0], c[mt][nt][1]);
                *(float2*)&g_msg_input[r0 * 256 + col] = v;
                float2 o = make_float2(fmaxf(v.x, 0.f), fmaxf(v.y, 0.f));
                *(float2*)&g_msgA[r0 * 256 + col] = o;
            }
            long r1 = r0 + 8;
            if (r1 < E) {
                float2 v = make_float2(c[mt][nt][2], c[mt][nt][3]);
                *(float2*)&g_msg_input[r1 * 256 + col] = v;
                float2 o = make_float2(fmaxf(v.x, 0.f), fmaxf(v.y, 0.f));
                *(float2*)&g_msgA[r1 * 256 + col] = o;
            }
        }
    }
}

__global__ __launch_bounds__(256)
void k_out_tf32(const float* __restrict__ x_nodes, const float* __restrict__ W_o,
                const float* __restrict__ b_o, int N) {
    __shared__ unsigned As[2][64][APAD];
    __shared__ unsigned Bs[2][16][BPAD];
    int tid = threadIdx.x;
    int lane = tid & 31, wid = tid >> 5;
    int gg = lane >> 2, tig = lane & 3;
    int wm = (wid & 1) * 32, wn = (wid >> 1) * 64;
    long row0 = (long)blockIdx.x * 64;

    float c[2][8][4];
#pragma unroll
    for (int mt = 0; mt < 2; mt++)
#pragma unroll
        for (int nt = 0; nt < 8; nt++)
#pragma unroll
            for (int r = 0; r < 4; r++) c[mt][nt][r] = 0.f;

    const int NT = 19;
    {
#pragma unroll
        for (int u = 0; u < 4; u++) {
            int i = tid + u * 256;
            int row = i >> 4, kk = i & 15;
            long r = row0 + row;
            float v = 0.f;
            if (r < N && kk < 291)
                v = (kk < 35) ? x_nodes[r * 35 + kk] : g_m[r * 256 + (kk - 35)];
            As[0][row][kk] = f2tf(v);
        }
#pragma unroll
        for (int u = 0; u < 4; u++) {
            int ff = tid + u * 256, krow = ff >> 6, cc = ff & 63;
            float4 bvv = make_float4(0, 0, 0, 0);
            if (krow < 291) bvv = *(const float4*)&W_o[krow * 256 + cc * 4];
            unsigned* q = &Bs[0][krow][cc * 4];
            q[0] = f2tf(bvv.x); q[1] = f2tf(bvv.y); q[2] = f2tf(bvv.z); q[3] = f2tf(bvv.w);
        }
    }
    __syncthreads();

    for (int kt = 0; kt < NT; kt++) {
        int cbuf = kt & 1, nbuf = cbuf ^ 1;
        float avs[4]; float4 bv[4];
        if (kt < NT - 1) {
            int k0 = (kt + 1) * 16;
#pragma unroll
            for (int u = 0; u < 4; u++) {
                int i = tid + u * 256;
                int row = i >> 4, kk = i & 15;
                long r = row0 + row; int gk = k0 + kk;
                float v = 0.f;
                if (r < N && gk < 291)
                    v = (gk < 35) ? x_nodes[r * 35 + gk] : g_m[r * 256 + (gk - 35)];
                avs[u] = v;
            }
#pragma unroll
            for (int u = 0; u < 4; u++) {
                int ff = tid + u * 256, krow = ff >> 6, cc = ff & 63;
                int gk = k0 + krow;
                bv[u] = make_float4(0, 0, 0, 0);
                if (gk < 291) bv[u] = *(const float4*)&W_o[gk * 256 + cc * 4];
            }
        }
#pragma unroll
        for (int ks = 0; ks < 16; ks += 8) {
            unsigned a[2][4], b[8][2];
#pragma unroll
            for (int mt = 0; mt < 2; mt++) {
                int m0 = wm + mt * 16 + gg;
                a[mt][0] = As[cbuf][m0][ks + tig];
                a[mt][1] = As[cbuf][m0 + 8][ks + tig];
                a[mt][2] = As[cbuf][m0][ks + tig + 4];
                a[mt][3] = As[cbuf][m0 + 8][ks + tig + 4];
            }
#pragma unroll
            for (int nt = 0; nt < 8; nt++) {
                int n0 = wn + nt * 8 + gg;
                b[nt][0] = Bs[cbuf][ks + tig][n0];
                b[nt][1] = Bs[cbuf][ks + tig + 4][n0];
            }
#pragma unroll
            for (int mt = 0; mt < 2; mt++)
#pragma unroll
                for (int nt = 0; nt < 8; nt++)
                    mma_tf32(c[mt][nt], a[mt], b[nt]);
        }
        if (kt < NT - 1) {
#pragma unroll
            for (int u = 0; u < 4; u++) {
                int i = tid + u * 256;
                int row = i >> 4, kk = i & 15;
                As[nbuf][row][kk] = f2tf(avs[u]);
            }
#pragma unroll
            for (int u = 0; u < 4; u++) {
                int ff = tid + u * 256, krow = ff >> 6, cc = ff & 63;
                unsigned* q = &Bs[nbuf][krow][cc * 4];
                q[0] = f2tf(bv[u].x); q[1] = f2tf(bv[u].y); q[2] = f2tf(bv[u].z); q[3] = f2tf(bv[u].w);
            }
        }
        __syncthreads();
    }

#pragma unroll
    for (int mt = 0; mt < 2; mt++) {
#pragma unroll
        for (int nt = 0; nt < 8; nt++) {
            int col = wn + nt * 8 + tig * 2;
            float b0v = b_o[col], b1v = b_o[col + 1];
            long r0 = row0 + wm + mt * 16 + gg;
            if (r0 < N) {
                float2 o;
                o.x = fmaxf(c[mt][nt][0] + b0v, 0.f);
                o.y = fmaxf(c[mt][nt][1] + b1v, 0.f);
                *(float2*)&g_h[r0 * 256 + col] = o;
            }
            long r1 = r0 + 8;
            if (r1 < N) {
                float2 o;
                o.x = fmaxf(c[mt][nt][2] + b0v, 0.f);
                o.y = fmaxf(c[mt][nt][3] + b1v, 0.f);
                *(float2*)&g_h[r1 * 256 + col] = o;
            }
        }
    }
}

// per-graph mean over sorted graph_ids
__global__ void k_mean(const int* __restrict__ gid, float* __restrict__ out, int N) {
    int g = blockIdx.x;
    int t = threadIdx.x;
    int lo = 0, hi = N;
    while (lo < hi) { int m = (lo + hi) >> 1; if (gid[m] < g) lo = m + 1; else hi = m; }
    int s = lo;
    hi = N;
    while (lo < hi) { int m = (lo + hi) >> 1; if (gid[m] < g + 1) lo = m + 1; else hi = m; }
    int e = lo;
    float sum = 0.f;
    for (int n = s; n < e; n++) sum += g_h[n * HDIM + t];
    float c = (float)((e - s) > 0 ? (e - s) : 1);
    out[g * HDIM + t] = sum / c;
}

// ---------------- launcher ----------------
extern "C" void kernel_launch(void* const* d_in, const int* in_sizes, int n_in,
                              void* d_out, int out_size) {
    const float* x_nodes = (const float*)d_in[0];
    const float* x_edges = (const float*)d_in[1];
    const float* tree_m  = (const float*)d_in[2];
    const float* W_i     = (const float*)d_in[3];
    const float* W_h     = (const float*)d_in[4];
    const float* W_o     = (const float*)d_in[5];
    const float* b_o     = (const float*)d_in[6];
    const int*   esrc    = (const int*)d_in[7];
    const int*   edst    = (const int*)d_in[8];
    const int*   tgt     = (const int*)d_in[11];
    const int*   teid    = (const int*)d_in[12];
    const int*   gid     = (const int*)d_in[13];

    int N = in_sizes[0] / 35;
    int E = in_sizes[1] / 5;
    int K = in_sizes[11];
    int G = out_size / HDIM;
    float* out = (float*)d_out;

    int* d_node_ptr; cudaGetSymbolAddress((void**)&d_node_ptr, g_node_ptr);
    int* d_bt_ptr;   cudaGetSymbolAddress((void**)&d_bt_ptr, g_bt_ptr);

    cudaFuncSetAttribute(k_bp_fused, cudaFuncAttributeMaxDynamicSharedMemorySize, BP_SMEM);

    // node in-edge CSR
    k_zero_cnt<<<(N + 255) / 256, 256>>>(N);
    k_count<<<(E + 255) / 256, 256>>>(edst, E);
    k_scan<<<1, 1024>>>(d_node_ptr, N, 1);
    k_place<<<(E + 255) / 256, 256>>>(edst, E);
    // backtrack CSR
    k_bt_count<<<(E + 255) / 256, 256>>>(esrc, edst, E);
    k_scan<<<1, 1024>>>(d_bt_ptr, E, 0);
    k_bt_fill<<<(E + 255) / 256, 256>>>(esrc, edst, E);

    k_convW<<<(HDIM * HDIM + 255) / 256, 256>>>(W_h);
    k_zero_alpha<<<(N * HDIM + 255) / 256, 256>>>(N * HDIM);
    k_edge_tf32<<<(E + 63) / 64, 256>>>(x_nodes, x_edges, W_i, esrc, E);
    k_scatter_alpha<<<(K * 256 + 255) / 256, 256>>>(tree_m, tgt, teid, K);

    // it0: A->B ; it1: B->A ; it2: A->B ; final m from B
    k_nodesum<<<(N + 3) / 4, 256>>>(0, 0, N);
    k_bp_fused<<<(E + 127) / 128, 512, BP_SMEM>>>(esrc, E, 0);
    k_nodesum<<<(N + 3) / 4, 256>>>(1, 0, N);
    k_bp_fused<<<(E + 127) / 128, 512, BP_SMEM>>>(esrc, E, 1);
    k_nodesum<<<(N + 3) / 4, 256>>>(0, 0, N);
    k_bp_fused<<<(E + 127) / 128, 512, BP_SMEM>>>(esrc, E, 0);
    k_nodesum<<<(N + 3) / 4, 256>>>(1, 1, N);

    k_out_tf32<<<(N + 63) / 64, 256>>>(x_nodes, W_o, b_o, N);
    k_mean<<<G, 256>>>(gid, out, N);
}

// round 10
// speedup vs baseline: 1.0913x; 1.0913x over previous
#include <cuda_runtime.h>

#define HDIM 256
#define MAX_E 200000
#define MAX_N 50000
#define MAX_BT (MAX_E * 8)

// ---------------- static scratch ----------------
__device__ float g_msg_input[MAX_E * HDIM];
__device__ float g_msgA[MAX_E * HDIM];
__device__ float g_msgB[MAX_E * HDIM];
__device__ float g_node_alpha[MAX_N * HDIM];
__device__ float g_ns[MAX_N * HDIM];
__device__ float g_m[MAX_N * HDIM];
__device__ float g_h[MAX_N * HDIM];
__device__ unsigned g_Wh[HDIM * HDIM];    // W_h pre-converted to tf32
__device__ int   g_cnt[MAX_E];
__device__ int   g_node_ptr[MAX_N + 1];
__device__ int   g_in_idx[MAX_E];
__device__ int   g_bt_ptr[MAX_E + 1];
__device__ int   g_bt_idx[MAX_BT];

// ---------------- helpers ----------------
__device__ __forceinline__ unsigned f2tf(float x) {
    unsigned u; asm("cvt.rna.tf32.f32 %0, %1;" : "=r"(u) : "f"(x)); return u;
}
__device__ __forceinline__ void mma_tf32(float* c, const unsigned* a, const unsigned* b) {
    asm volatile(
        "mma.sync.aligned.m16n8k8.row.col.f32.tf32.tf32.f32 "
        "{%0,%1,%2,%3}, {%4,%5,%6,%7}, {%8,%9}, {%0,%1,%2,%3};\n"
        : "+f"(c[0]), "+f"(c[1]), "+f"(c[2]), "+f"(c[3])
        : "r"(a[0]), "r"(a[1]), "r"(a[2]), "r"(a[3]), "r"(b[0]), "r"(b[1]));
}

// ---------------- CSR builds ----------------
__global__ void k_zero_cnt(int n) {
    int i = blockIdx.x * blockDim.x + threadIdx.x;
    if (i < n) g_cnt[i] = 0;
}
__global__ void k_count(const int* __restrict__ edst, int E) {
    int e = blockIdx.x * blockDim.x + threadIdx.x;
    if (e < E) atomicAdd(&g_cnt[edst[e]], 1);
}
__global__ void k_scan(int* __restrict__ ptr, int n, int rezero) {
    __shared__ int sh[1024];
    __shared__ int carry;
    int tid = threadIdx.x;
    if (tid == 0) { carry = 0; ptr[0] = 0; }
    __syncthreads();
    for (int base = 0; base < n; base += 1024) {
        int i = base + tid;
        int v = (i < n) ? g_cnt[i] : 0;
        sh[tid] = v; __syncthreads();
        for (int off = 1; off < 1024; off <<= 1) {
            int add = (tid >= off) ? sh[tid - off] : 0;
            __syncthreads();
            sh[tid] += add; __syncthreads();
        }
        if (i < n) { ptr[i + 1] = carry + sh[tid]; if (rezero) g_cnt[i] = 0; }
        __syncthreads();
        if (tid == 0) carry += sh[1023];
        __syncthreads();
    }
}
__global__ void k_place(const int* __restrict__ edst, int E) {
    int e = blockIdx.x * blockDim.x + threadIdx.x;
    if (e >= E) return;
    int v = edst[e];
    int pos = atomicAdd(&g_cnt[v], 1);
    g_in_idx[g_node_ptr[v] + pos] = e;
}
__global__ void k_bt_count(const int* __restrict__ esrc, const int* __restrict__ edst, int E) {
    int e = blockIdx.x * blockDim.x + threadIdx.x;
    if (e >= E) return;
    int sv = esrc[e], dv = edst[e];
    int cnt = 0;
    for (int j = g_node_ptr[sv]; j < g_node_ptr[sv + 1]; j++)
        if (esrc[g_in_idx[j]] == dv) cnt++;
    g_cnt[e] = cnt;
}
__global__ void k_bt_fill(const int* __restrict__ esrc, const int* __restrict__ edst, int E) {
    int e = blockIdx.x * blockDim.x + threadIdx.x;
    if (e >= E) return;
    int sv = esrc[e], dv = edst[e];
    int k = g_bt_ptr[e];
    for (int j = g_node_ptr[sv]; j < g_node_ptr[sv + 1]; j++) {
        int e2 = g_in_idx[j];
        if (esrc[e2] == dv && k < MAX_BT) g_bt_idx[k++] = e2;
    }
}

// ---------------- misc ----------------
__global__ void k_zero_alpha(int n) {
    int i = blockIdx.x * blockDim.x + threadIdx.x;
    if (i < n) g_node_alpha[i] = 0.f;
}
__global__ void k_scatter_alpha(const float* __restrict__ tree_m,
                                const int* __restrict__ tgt,
                                const int* __restrict__ teid, int K) {
    int i = blockIdx.x * blockDim.x + threadIdx.x;
    int k = i >> 8, h = i & 255;
    if (k >= K) return;
    atomicAdd(&g_node_alpha[tgt[k] * HDIM + h], tree_m[teid[k] * HDIM + h]);
}
__global__ void k_convW(const float* __restrict__ W_h) {
    int i = blockIdx.x * blockDim.x + threadIdx.x;
    if (i < HDIM * HDIM) g_Wh[i] = f2tf(W_h[i]);
}

// ---------------- per-node sum: out[v] = alpha[v] + sum msg_in[in(v)] ----------------
__global__ __launch_bounds__(256)
void k_nodesum(int buf, int to_m, int N) {
    const float* __restrict__ msg_in = buf ? g_msgB : g_msgA;
    float* __restrict__ outp = to_m ? g_m : g_ns;
    int v = blockIdx.x * 4 + (threadIdx.x >> 6);
    if (v >= N) return;
    int t4 = (threadIdx.x & 63) * 4;
    float4 acc = *(const float4*)&g_node_alpha[(long)v * HDIM + t4];
    int s = g_node_ptr[v], en = g_node_ptr[v + 1];
    int i = s;
    for (; i + 4 <= en; i += 4) {
        int i0 = g_in_idx[i], i1 = g_in_idx[i + 1], i2 = g_in_idx[i + 2], i3 = g_in_idx[i + 3];
        float4 v0 = *(const float4*)&msg_in[(long)i0 * HDIM + t4];
        float4 v1 = *(const float4*)&msg_in[(long)i1 * HDIM + t4];
        float4 v2 = *(const float4*)&msg_in[(long)i2 * HDIM + t4];
        float4 v3 = *(const float4*)&msg_in[(long)i3 * HDIM + t4];
        acc.x += v0.x + v1.x + v2.x + v3.x;
        acc.y += v0.y + v1.y + v2.y + v3.y;
        acc.z += v0.z + v1.z + v2.z + v3.z;
        acc.w += v0.w + v1.w + v2.w + v3.w;
    }
    for (; i < en; i++) {
        float4 vv = *(const float4*)&msg_in[(long)g_in_idx[i] * HDIM + t4];
        acc.x += vv.x; acc.y += vv.y; acc.z += vv.z; acc.w += vv.w;
    }
    *(float4*)&outp[(long)v * HDIM + t4] = acc;
}

// ---------------- fused BP: BM=64 x BN=256, 256 threads, double-buffered B ----------------
#define AS(r, c) As[(r) * 260 + (c)]
#define BS(b, r, c) Bs[(b) * (16 * 264) + (r) * 264 + (c)]
#define BP_SMEM ((64 * 260 + 2 * 16 * 264) * 4)

__global__ __launch_bounds__(256, 2)
void k_bp_fused(const int* __restrict__ esrc, int E, int buf) {
    const float* __restrict__ msg_in  = buf ? g_msgB : g_msgA;
    float*       __restrict__ msg_out = buf ? g_msgA : g_msgB;

    extern __shared__ unsigned smem_u[];
    unsigned* As = smem_u;             // [64][260]
    unsigned* Bs = smem_u + 64 * 260;  // [2][16][264]

    int tid = threadIdx.x;
    int lane = tid & 31, wid = tid >> 5;
    int gg = lane >> 2, tig = lane & 3;
    int wm = (wid & 1) * 32, wn = (wid >> 1) * 64;
    long row0 = (long)blockIdx.x * 64;

    // ---- phase 1: A[e] = ns[src[e]] - (rare) backtrack rows ----
    {
        int grp = tid >> 6;
        int t4  = (tid & 63) * 4;
#pragma unroll
        for (int ib = 0; ib < 16; ib += 4) {
            float4 v[4];
            int rrs[4];
#pragma unroll
            for (int u = 0; u < 4; u++) {
                int rr = grp + (ib + u) * 4;
                rrs[u] = rr;
                long e = row0 + rr;
                if (e < E) {
                    int sv = esrc[e];
                    v[u] = *(const float4*)&g_ns[(long)sv * HDIM + t4];
                } else {
                    v[u] = make_float4(0, 0, 0, 0);
                }
            }
#pragma unroll
            for (int u = 0; u < 4; u++) {
                long e = row0 + rrs[u];
                if (e < E) {
                    int b0 = g_bt_ptr[e], b1 = g_bt_ptr[e + 1];
                    for (int j = b0; j < b1; j++) {
                        float4 w = *(const float4*)&msg_in[(long)g_bt_idx[j] * HDIM + t4];
                        v[u].x -= w.x; v[u].y -= w.y; v[u].z -= w.z; v[u].w -= w.w;
                    }
                }
                uint4 st;
                st.x = f2tf(v[u].x); st.y = f2tf(v[u].y); st.z = f2tf(v[u].z); st.w = f2tf(v[u].w);
                *(uint4*)&AS(rrs[u], t4) = st;
            }
        }
    }

    float c[2][8][4];
#pragma unroll
    for (int mt = 0; mt < 2; mt++)
#pragma unroll
        for (int nt = 0; nt < 8; nt++)
#pragma unroll
            for (int r = 0; r < 4; r++) c[mt][nt][r] = 0.f;

    // preload B tile 0 (16x256 tf32 = 1024 uint4, 4 per thread)
    {
#pragma unroll
        for (int u = 0; u < 4; u++) {
            int idx = tid + u * 256;
            int krow = idx >> 6, cc4 = idx & 63;
            *(uint4*)&BS(0, krow, cc4 * 4) = *(const uint4*)&g_Wh[krow * 256 + cc4 * 4];
        }
    }
    __syncthreads();

    // ---- phase 2: GEMM over 16 k-tiles, double-buffered B, 1 BAR/tile ----
    for (int kt = 0; kt < 16; kt++) {
        int cbuf = kt & 1, nbuf = cbuf ^ 1;
        if (kt < 15) {
            int k0 = (kt + 1) * 16;
#pragma unroll
            for (int u = 0; u < 4; u++) {
                int idx = tid + u * 256;
                int krow = idx >> 6, cc4 = idx & 63;
                *(uint4*)&BS(nbuf, krow, cc4 * 4) = *(const uint4*)&g_Wh[(k0 + krow) * 256 + cc4 * 4];
            }
        }
#pragma unroll
        for (int ks = 0; ks < 16; ks += 8) {
            unsigned a[2][4], b[8][2];
            int kbase = kt * 16 + ks;
#pragma unroll
            for (int mt = 0; mt < 2; mt++) {
                int m0 = wm + mt * 16 + gg;
                a[mt][0] = AS(m0,     kbase + tig);
                a[mt][1] = AS(m0 + 8, kbase + tig);
                a[mt][2] = AS(m0,     kbase + tig + 4);
                a[mt][3] = AS(m0 + 8, kbase + tig + 4);
            }
#pragma unroll
            for (int nt = 0; nt < 8; nt++) {
                int n0 = wn + nt * 8 + gg;
                b[nt][0] = BS(cbuf, ks + tig,     n0);
                b[nt][1] = BS(cbuf, ks + tig + 4, n0);
            }
#pragma unroll
            for (int mt = 0; mt < 2; mt++)
#pragma unroll
                for (int nt = 0; nt < 8; nt++)
                    mma_tf32(c[mt][nt], a[mt], b[nt]);
        }
        __syncthreads();
    }

    // ---- epilogue: msg_out = relu(msg_input + acc) ----
#pragma unroll
    for (int mt = 0; mt < 2; mt++) {
#pragma unroll
        for (int nt = 0; nt < 8; nt++) {
            int col = wn + nt * 8 + tig * 2;
            long r0 = row0 + wm + mt * 16 + gg;
            if (r0 < E) {
                float2 mi = *(const float2*)&g_msg_input[r0 * 256 + col];
                float2 o;
                o.x = fmaxf(mi.x + c[mt][nt][0], 0.f);
                o.y = fmaxf(mi.y + c[mt][nt][1], 0.f);
                *(float2*)&msg_out[r0 * 256 + col] = o;
            }
            long r1 = r0 + 8;
            if (r1 < E) {
                float2 mi = *(const float2*)&g_msg_input[r1 * 256 + col];
                float2 o;
                o.x = fmaxf(mi.x + c[mt][nt][2], 0.f);
                o.y = fmaxf(mi.y + c[mt][nt][3], 0.f);
                *(float2*)&msg_out[r1 * 256 + col] = o;
            }
        }
    }
}

// ---------------- tf32 GEMM kernels (edge input, output) ----------------
#define APAD 20
#define BPAD 264

__global__ __launch_bounds__(256)
void k_edge_tf32(const float* __restrict__ x_nodes, const float* __restrict__ x_edges,
                 const float* __restrict__ W_i, const int* __restrict__ esrc, int E) {
    __shared__ unsigned As[2][64][APAD];
    __shared__ unsigned Bs[2][16][BPAD];
    int tid = threadIdx.x;
    int lane = tid & 31, wid = tid >> 5;
    int gg = lane >> 2, tig = lane & 3;
    int wm = (wid & 1) * 32, wn = (wid >> 1) * 64;
    long row0 = (long)blockIdx.x * 64;

    float c[2][8][4];
#pragma unroll
    for (int mt = 0; mt < 2; mt++)
#pragma unroll
        for (int nt = 0; nt < 8; nt++)
#pragma unroll
            for (int r = 0; r < 4; r++) c[mt][nt][r] = 0.f;

    const int NT = 3;
    {
#pragma unroll
        for (int u = 0; u < 4; u++) {
            int i = tid + u * 256;
            int row = i >> 4, kk = i & 15;
            long r = row0 + row;
            float v = 0.f;
            if (r < E && kk < 40)
                v = (kk < 35) ? x_nodes[(long)esrc[r] * 35 + kk] : x_edges[r * 5 + (kk - 35)];
            As[0][row][kk] = f2tf(v);
        }
#pragma unroll
        for (int u = 0; u < 4; u++) {
            int ff = tid + u * 256, krow = ff >> 6, cc = ff & 63;
            float4 bvv = make_float4(0, 0, 0, 0);
            if (krow < 40) bvv = *(const float4*)&W_i[krow * 256 + cc * 4];
            unsigned* q = &Bs[0][krow][cc * 4];
            q[0] = f2tf(bvv.x); q[1] = f2tf(bvv.y); q[2] = f2tf(bvv.z); q[3] = f2tf(bvv.w);
        }
    }
    __syncthreads();

    for (int kt = 0; kt < NT; kt++) {
        int cbuf = kt & 1, nbuf = cbuf ^ 1;
        float avs[4]; float4 bv[4];
        if (kt < NT - 1) {
            int k0 = (kt + 1) * 16;
#pragma unroll
            for (int u = 0; u < 4; u++) {
                int i = tid + u * 256;
                int row = i >> 4, kk = i & 15;
                long r = row0 + row; int gk = k0 + kk;
                float v = 0.f;
                if (r < E && gk < 40)
                    v = (gk < 35) ? x_nodes[(long)esrc[r] * 35 + gk] : x_edges[r * 5 + (gk - 35)];
                avs[u] = v;
            }
#pragma unroll
            for (int u = 0; u < 4; u++) {
                int ff = tid + u * 256, krow = ff >> 6, cc = ff & 63;
                int gk = k0 + krow;
                bv[u] = make_float4(0, 0, 0, 0);
                if (gk < 40) bv[u] = *(const float4*)&W_i[gk * 256 + cc * 4];
            }
        }
#pragma unroll
        for (int ks = 0; ks < 16; ks += 8) {
            unsigned a[2][4], b[8][2];
#pragma unroll
            for (int mt = 0; mt < 2; mt++) {
                int m0 = wm + mt * 16 + gg;
                a[mt][0] = As[cbuf][m0][ks + tig];
                a[mt][1] = As[cbuf][m0 + 8][ks + tig];
                a[mt][2] = As[cbuf][m0][ks + tig + 4];
                a[mt][3] = As[cbuf][m0 + 8][ks + tig + 4];
            }
#pragma unroll
            for (int nt = 0; nt < 8; nt++) {
                int n0 = wn + nt * 8 + gg;
                b[nt][0] = Bs[cbuf][ks + tig][n0];
                b[nt][1] = Bs[cbuf][ks + tig + 4][n0];
            }
#pragma unroll
            for (int mt = 0; mt < 2; mt++)
#pragma unroll
                for (int nt = 0; nt < 8; nt++)
                    mma_tf32(c[mt][nt], a[mt], b[nt]);
        }
        if (kt < NT - 1) {
#pragma unroll
            for (int u = 0; u < 4; u++) {
                int i = tid + u * 256;
                int row = i >> 4, kk = i & 15;
                As[nbuf][row][kk] = f2tf(avs[u]);
            }
#pragma unroll
            for (int u = 0; u < 4; u++) {
                int ff = tid + u * 256, krow = ff >> 6, cc = ff & 63;
                unsigned* q = &Bs[nbuf][krow][cc * 4];
                q[0] = f2tf(bv[u].x); q[1] = f2tf(bv[u].y); q[2] = f2tf(bv[u].z); q[3] = f2tf(bv[u].w);
            }
        }
        __syncthreads();
    }

#pragma unroll
    for (int mt = 0; mt < 2; mt++) {
#pragma unroll
        for (int nt = 0; nt < 8; nt++) {
            int col = wn + nt * 8 + tig * 2;
            long r0 = row0 + wm + mt * 16 + gg;
            if (r0 < E) {
                float2 v = make_float2(c[mt][nt][0], c[mt][nt][1]);
                *(float2*)&g_msg_input[r0 * 256 + col] = v;
                float2 o = make_float2(fmaxf(v.x, 0.f), fmaxf(v.y, 0.f));
                *(float2*)&g_msgA[r0 * 256 + col] = o;
            }
            long r1 = r0 + 8;
            if (r1 < E) {
                float2 v = make_float2(c[mt][nt][2], c[mt][nt][3]);
                *(float2*)&g_msg_input[r1 * 256 + col] = v;
                float2 o = make_float2(fmaxf(v.x, 0.f), fmaxf(v.y, 0.f));
                *(float2*)&g_msgA[r1 * 256 + col] = o;
            }
        }
    }
}

__global__ __launch_bounds__(256)
void k_out_tf32(const float* __restrict__ x_nodes, const float* __restrict__ W_o,
                const float* __restrict__ b_o, int N) {
    __shared__ unsigned As[2][64][APAD];
    __shared__ unsigned Bs[2][16][BPAD];
    int tid = threadIdx.x;
    int lane = tid & 31, wid = tid >> 5;
    int gg = lane >> 2, tig = lane & 3;
    int wm = (wid & 1) * 32, wn = (wid >> 1) * 64;
    long row0 = (long)blockIdx.x * 64;

    float c[2][8][4];
#pragma unroll
    for (int mt = 0; mt < 2; mt++)
#pragma unroll
        for (int nt = 0; nt < 8; nt++)
#pragma unroll
            for (int r = 0; r < 4; r++) c[mt][nt][r] = 0.f;

    const int NT = 19;
    {
#pragma unroll
        for (int u = 0; u < 4; u++) {
            int i = tid + u * 256;
            int row = i >> 4, kk = i & 15;
            long r = row0 + row;
            float v = 0.f;
            if (r < N && kk < 291)
                v = (kk < 35) ? x_nodes[r * 35 + kk] : g_m[r * 256 + (kk - 35)];
            As[0][row][kk] = f2tf(v);
        }
#pragma unroll
        for (int u = 0; u < 4; u++) {
            int ff = tid + u * 256, krow = ff >> 6, cc = ff & 63;
            float4 bvv = make_float4(0, 0, 0, 0);
            if (krow < 291) bvv = *(const float4*)&W_o[krow * 256 + cc * 4];
            unsigned* q = &Bs[0][krow][cc * 4];
            q[0] = f2tf(bvv.x); q[1] = f2tf(bvv.y); q[2] = f2tf(bvv.z); q[3] = f2tf(bvv.w);
        }
    }
    __syncthreads();

    for (int kt = 0; kt < NT; kt++) {
        int cbuf = kt & 1, nbuf = cbuf ^ 1;
        float avs[4]; float4 bv[4];
        if (kt < NT - 1) {
            int k0 = (kt + 1) * 16;
#pragma unroll
            for (int u = 0; u < 4; u++) {
                int i = tid + u * 256;
                int row = i >> 4, kk = i & 15;
                long r = row0 + row; int gk = k0 + kk;
                float v = 0.f;
                if (r < N && gk < 291)
                    v = (gk < 35) ? x_nodes[r * 35 + gk] : g_m[r * 256 + (gk - 35)];
                avs[u] = v;
            }
#pragma unroll
            for (int u = 0; u < 4; u++) {
                int ff = tid + u * 256, krow = ff >> 6, cc = ff & 63;
                int gk = k0 + krow;
                bv[u] = make_float4(0, 0, 0, 0);
                if (gk < 291) bv[u] = *(const float4*)&W_o[gk * 256 + cc * 4];
            }
        }
#pragma unroll
        for (int ks = 0; ks < 16; ks += 8) {
            unsigned a[2][4], b[8][2];
#pragma unroll
            for (int mt = 0; mt < 2; mt++) {
                int m0 = wm + mt * 16 + gg;
                a[mt][0] = As[cbuf][m0][ks + tig];
                a[mt][1] = As[cbuf][m0 + 8][ks + tig];
                a[mt][2] = As[cbuf][m0][ks + tig + 4];
                a[mt][3] = As[cbuf][m0 + 8][ks + tig + 4];
            }
#pragma unroll
            for (int nt = 0; nt < 8; nt++) {
                int n0 = wn + nt * 8 + gg;
                b[nt][0] = Bs[cbuf][ks + tig][n0];
                b[nt][1] = Bs[cbuf][ks + tig + 4][n0];
            }
#pragma unroll
            for (int mt = 0; mt < 2; mt++)
#pragma unroll
                for (int nt = 0; nt < 8; nt++)
                    mma_tf32(c[mt][nt], a[mt], b[nt]);
        }
        if (kt < NT - 1) {
#pragma unroll
            for (int u = 0; u < 4; u++) {
                int i = tid + u * 256;
                int row = i >> 4, kk = i & 15;
                As[nbuf][row][kk] = f2tf(avs[u]);
            }
#pragma unroll
            for (int u = 0; u < 4; u++) {
                int ff = tid + u * 256, krow = ff >> 6, cc = ff & 63;
                unsigned* q = &Bs[nbuf][krow][cc * 4];
                q[0] = f2tf(bv[u].x); q[1] = f2tf(bv[u].y); q[2] = f2tf(bv[u].z); q[3] = f2tf(bv[u].w);
            }
        }
        __syncthreads();
    }

#pragma unroll
    for (int mt = 0; mt < 2; mt++) {
#pragma unroll
        for (int nt = 0; nt < 8; nt++) {
            int col = wn + nt * 8 + tig * 2;
            float b0v = b_o[col], b1v = b_o[col + 1];
            long r0 = row0 + wm + mt * 16 + gg;
            if (r0 < N) {
                float2 o;
                o.x = fmaxf(c[mt][nt][0] + b0v, 0.f);
                o.y = fmaxf(c[mt][nt][1] + b1v, 0.f);
                *(float2*)&g_h[r0 * 256 + col] = o;
            }
            long r1 = r0 + 8;
            if (r1 < N) {
                float2 o;
                o.x = fmaxf(c[mt][nt][2] + b0v, 0.f);
                o.y = fmaxf(c[mt][nt][3] + b1v, 0.f);
                *(float2*)&g_h[r1 * 256 + col] = o;
            }
        }
    }
}

// per-graph mean over sorted graph_ids
__global__ void k_mean(const int* __restrict__ gid, float* __restrict__ out, int N) {
    int g = blockIdx.x;
    int t = threadIdx.x;
    int lo = 0, hi = N;
    while (lo < hi) { int m = (lo + hi) >> 1; if (gid[m] < g) lo = m + 1; else hi = m; }
    int s = lo;
    hi = N;
    while (lo < hi) { int m = (lo + hi) >> 1; if (gid[m] < g + 1) lo = m + 1; else hi = m; }
    int e = lo;
    float sum = 0.f;
    for (int n = s; n < e; n++) sum += g_h[n * HDIM + t];
    float c = (float)((e - s) > 0 ? (e - s) : 1);
    out[g * HDIM + t] = sum / c;
}

// ---------------- launcher ----------------
extern "C" void kernel_launch(void* const* d_in, const int* in_sizes, int n_in,
                              void* d_out, int out_size) {
    const float* x_nodes = (const float*)d_in[0];
    const float* x_edges = (const float*)d_in[1];
    const float* tree_m  = (const float*)d_in[2];
    const float* W_i     = (const float*)d_in[3];
    const float* W_h     = (const float*)d_in[4];
    const float* W_o     = (const float*)d_in[5];
    const float* b_o     = (const float*)d_in[6];
    const int*   esrc    = (const int*)d_in[7];
    const int*   edst    = (const int*)d_in[8];
    const int*   tgt     = (const int*)d_in[11];
    const int*   teid    = (const int*)d_in[12];
    const int*   gid     = (const int*)d_in[13];

    int N = in_sizes[0] / 35;
    int E = in_sizes[1] / 5;
    int K = in_sizes[11];
    int G = out_size / HDIM;
    float* out = (float*)d_out;

    int* d_node_ptr; cudaGetSymbolAddress((void**)&d_node_ptr, g_node_ptr);
    int* d_bt_ptr;   cudaGetSymbolAddress((void**)&d_bt_ptr, g_bt_ptr);

    cudaFuncSetAttribute(k_bp_fused, cudaFuncAttributeMaxDynamicSharedMemorySize, BP_SMEM);

    // node in-edge CSR
    k_zero_cnt<<<(N + 255) / 256, 256>>>(N);
    k_count<<<(E + 255) / 256, 256>>>(edst, E);
    k_scan<<<1, 1024>>>(d_node_ptr, N, 1);
    k_place<<<(E + 255) / 256, 256>>>(edst, E);
    // backtrack CSR
    k_bt_count<<<(E + 255) / 256, 256>>>(esrc, edst, E);
    k_scan<<<1, 1024>>>(d_bt_ptr, E, 0);
    k_bt_fill<<<(E + 255) / 256, 256>>>(esrc, edst, E);

    k_convW<<<(HDIM * HDIM + 255) / 256, 256>>>(W_h);
    k_zero_alpha<<<(N * HDIM + 255) / 256, 256>>>(N * HDIM);
    k_edge_tf32<<<(E + 63) / 64, 256>>>(x_nodes, x_edges, W_i, esrc, E);
    k_scatter_alpha<<<(K * 256 + 255) / 256, 256>>>(tree_m, tgt, teid, K);

    // it0: A->B ; it1: B->A ; it2: A->B ; final m from B
    k_nodesum<<<(N + 3) / 4, 256>>>(0, 0, N);
    k_bp_fused<<<(E + 63) / 64, 256, BP_SMEM>>>(esrc, E, 0);
    k_nodesum<<<(N + 3) / 4, 256>>>(1, 0, N);
    k_bp_fused<<<(E + 63) / 64, 256, BP_SMEM>>>(esrc, E, 1);
    k_nodesum<<<(N + 3) / 4, 256>>>(0, 0, N);
    k_bp_fused<<<(E + 63) / 64, 256, BP_SMEM>>>(esrc, E, 0);
    k_nodesum<<<(N + 3) / 4, 256>>>(1, 1, N);

    k_out_tf32<<<(N + 63) / 64, 256>>>(x_nodes, W_o, b_o, N);
    k_mean<<<G, 256>>>(gid, out, N);
}

// round 11
// speedup vs baseline: 1.2206x; 1.1185x over previous
#include <cuda_runtime.h>
#include <cuda_fp16.h>

#define HDIM 256
#define MAX_E 200000
#define MAX_N 50000
#define MAX_BT (MAX_E * 8)

// ---------------- static scratch ----------------
__device__ float    g_msg_input[MAX_E * HDIM];
__device__ unsigned g_msgA[MAX_E * HDIM / 2];   // fp16 half2-packed
__device__ unsigned g_msgB[MAX_E * HDIM / 2];   // fp16 half2-packed
__device__ float    g_node_alpha[MAX_N * HDIM];
__device__ unsigned g_ns[MAX_N * HDIM / 2];     // fp16 half2-packed
__device__ float    g_m[MAX_N * HDIM];
__device__ float    g_h[MAX_N * HDIM];
__device__ unsigned g_Wh[HDIM * HDIM];          // W_h pre-converted to tf32
__device__ int      g_cnt[MAX_E];
__device__ int      g_node_ptr[MAX_N + 1];
__device__ int      g_in_idx[MAX_E];
__device__ int      g_bt_ptr[MAX_E + 1];
__device__ int      g_bt_idx[MAX_BT];

// ---------------- helpers ----------------
__device__ __forceinline__ unsigned f2tf(float x) {
    unsigned u; asm("cvt.rna.tf32.f32 %0, %1;" : "=r"(u) : "f"(x)); return u;
}
__device__ __forceinline__ float2 h2f(unsigned u) {
    __half2 h = *reinterpret_cast<__half2*>(&u);
    return __half22float2(h);
}
__device__ __forceinline__ unsigned f2h(float2 v) {
    __half2 h = __float22half2_rn(v);
    return *reinterpret_cast<unsigned*>(&h);
}
__device__ __forceinline__ float4 ldh4(const unsigned* p, long idx) {  // idx multiple of 4
    uint2 u = *(const uint2*)&p[idx >> 1];
    float2 a = h2f(u.x), b = h2f(u.y);
    return make_float4(a.x, a.y, b.x, b.y);
}
__device__ __forceinline__ void mma_tf32(float* c, const unsigned* a, const unsigned* b) {
    asm volatile(
        "mma.sync.aligned.m16n8k8.row.col.f32.tf32.tf32.f32 "
        "{%0,%1,%2,%3}, {%4,%5,%6,%7}, {%8,%9}, {%0,%1,%2,%3};\n"
        : "+f"(c[0]), "+f"(c[1]), "+f"(c[2]), "+f"(c[3])
        : "r"(a[0]), "r"(a[1]), "r"(a[2]), "r"(a[3]), "r"(b[0]), "r"(b[1]));
}

// ---------------- CSR builds ----------------
__global__ void k_zero_cnt(int n) {
    int i = blockIdx.x * blockDim.x + threadIdx.x;
    if (i < n) g_cnt[i] = 0;
}
__global__ void k_count(const int* __restrict__ edst, int E) {
    int e = blockIdx.x * blockDim.x + threadIdx.x;
    if (e < E) atomicAdd(&g_cnt[edst[e]], 1);
}
__global__ void k_scan(int* __restrict__ ptr, int n, int rezero) {
    __shared__ int sh[1024];
    __shared__ int carry;
    int tid = threadIdx.x;
    if (tid == 0) { carry = 0; ptr[0] = 0; }
    __syncthreads();
    for (int base = 0; base < n; base += 1024) {
        int i = base + tid;
        int v = (i < n) ? g_cnt[i] : 0;
        sh[tid] = v; __syncthreads();
        for (int off = 1; off < 1024; off <<= 1) {
            int add = (tid >= off) ? sh[tid - off] : 0;
            __syncthreads();
            sh[tid] += add; __syncthreads();
        }
        if (i < n) { ptr[i + 1] = carry + sh[tid]; if (rezero) g_cnt[i] = 0; }
        __syncthreads();
        if (tid == 0) carry += sh[1023];
        __syncthreads();
    }
}
__global__ void k_place(const int* __restrict__ edst, int E) {
    int e = blockIdx.x * blockDim.x + threadIdx.x;
    if (e >= E) return;
    int v = edst[e];
    int pos = atomicAdd(&g_cnt[v], 1);
    g_in_idx[g_node_ptr[v] + pos] = e;
}
__global__ void k_bt_count(const int* __restrict__ esrc, const int* __restrict__ edst, int E) {
    int e = blockIdx.x * blockDim.x + threadIdx.x;
    if (e >= E) return;
    int sv = esrc[e], dv = edst[e];
    int cnt = 0;
    for (int j = g_node_ptr[sv]; j < g_node_ptr[sv + 1]; j++)
        if (esrc[g_in_idx[j]] == dv) cnt++;
    g_cnt[e] = cnt;
}
__global__ void k_bt_fill(const int* __restrict__ esrc, const int* __restrict__ edst, int E) {
    int e = blockIdx.x * blockDim.x + threadIdx.x;
    if (e >= E) return;
    int sv = esrc[e], dv = edst[e];
    int k = g_bt_ptr[e];
    for (int j = g_node_ptr[sv]; j < g_node_ptr[sv + 1]; j++) {
        int e2 = g_in_idx[j];
        if (esrc[e2] == dv && k < MAX_BT) g_bt_idx[k++] = e2;
    }
}

// ---------------- misc ----------------
__global__ void k_zero_alpha(int n) {
    int i = blockIdx.x * blockDim.x + threadIdx.x;
    if (i < n) g_node_alpha[i] = 0.f;
}
__global__ void k_scatter_alpha(const float* __restrict__ tree_m,
                                const int* __restrict__ tgt,
                                const int* __restrict__ teid, int K) {
    int i = blockIdx.x * blockDim.x + threadIdx.x;
    int k = i >> 8, h = i & 255;
    if (k >= K) return;
    atomicAdd(&g_node_alpha[tgt[k] * HDIM + h], tree_m[teid[k] * HDIM + h]);
}
__global__ void k_convW(const float* __restrict__ W_h) {
    int i = blockIdx.x * blockDim.x + threadIdx.x;
    if (i < HDIM * HDIM) g_Wh[i] = f2tf(W_h[i]);
}

// ---------------- per-node sum: out[v] = alpha[v] + sum msg_in[in(v)] ----------------
__global__ __launch_bounds__(256)
void k_nodesum(int buf, int to_m, int N) {
    const unsigned* __restrict__ msg_in = buf ? g_msgB : g_msgA;
    int v = blockIdx.x * 4 + (threadIdx.x >> 6);
    if (v >= N) return;
    int t4 = (threadIdx.x & 63) * 4;
    float4 acc = *(const float4*)&g_node_alpha[(long)v * HDIM + t4];
    int s = g_node_ptr[v], en = g_node_ptr[v + 1];
    int i = s;
    for (; i + 4 <= en; i += 4) {
        int i0 = g_in_idx[i], i1 = g_in_idx[i + 1], i2 = g_in_idx[i + 2], i3 = g_in_idx[i + 3];
        float4 v0 = ldh4(msg_in, (long)i0 * HDIM + t4);
        float4 v1 = ldh4(msg_in, (long)i1 * HDIM + t4);
        float4 v2 = ldh4(msg_in, (long)i2 * HDIM + t4);
        float4 v3 = ldh4(msg_in, (long)i3 * HDIM + t4);
        acc.x += v0.x + v1.x + v2.x + v3.x;
        acc.y += v0.y + v1.y + v2.y + v3.y;
        acc.z += v0.z + v1.z + v2.z + v3.z;
        acc.w += v0.w + v1.w + v2.w + v3.w;
    }
    for (; i < en; i++) {
        float4 vv = ldh4(msg_in, (long)g_in_idx[i] * HDIM + t4);
        acc.x += vv.x; acc.y += vv.y; acc.z += vv.z; acc.w += vv.w;
    }
    if (to_m) {
        *(float4*)&g_m[(long)v * HDIM + t4] = acc;
    } else {
        uint2 st;
        st.x = f2h(make_float2(acc.x, acc.y));
        st.y = f2h(make_float2(acc.z, acc.w));
        *(uint2*)&g_ns[((long)v * HDIM + t4) >> 1] = st;
    }
}

// ---------------- fused BP: BM=64 x BN=256, 256 threads (R8 config + tf32 W + fp16 I/O) ----------------
#define AS(r, c) As[(r) * 260 + (c)]
#define BS(r, c) Bs[(r) * 264 + (c)]
#define BP_SMEM ((64 * 260 + 16 * 264) * 4)

__global__ __launch_bounds__(256, 2)
void k_bp_fused(const int* __restrict__ esrc, int E, int buf) {
    const unsigned* __restrict__ msg_in  = buf ? g_msgB : g_msgA;
    unsigned*       __restrict__ msg_out = buf ? g_msgA : g_msgB;

    extern __shared__ unsigned smem_u[];
    unsigned* As = smem_u;             // [64][260]
    unsigned* Bs = smem_u + 64 * 260;  // [16][264]

    int tid = threadIdx.x;
    int lane = tid & 31, wid = tid >> 5;
    int gg = lane >> 2, tig = lane & 3;
    int wm = (wid & 1) * 32, wn = (wid >> 1) * 64;
    long row0 = (long)blockIdx.x * 64;

    // ---- phase 1: A[e] = ns[src[e]] - (rare) backtrack rows ----
    {
        int grp = tid >> 6;
        int t4  = (tid & 63) * 4;
#pragma unroll
        for (int ib = 0; ib < 16; ib += 4) {
            float4 v[4];
            int rrs[4];
#pragma unroll
            for (int u = 0; u < 4; u++) {
                int rr = grp + (ib + u) * 4;
                rrs[u] = rr;
                long e = row0 + rr;
                if (e < E) {
                    int sv = esrc[e];
                    v[u] = ldh4(g_ns, (long)sv * HDIM + t4);
                } else {
                    v[u] = make_float4(0, 0, 0, 0);
                }
            }
#pragma unroll
            for (int u = 0; u < 4; u++) {
                long e = row0 + rrs[u];
                if (e < E) {
                    int b0 = g_bt_ptr[e], b1 = g_bt_ptr[e + 1];
                    for (int j = b0; j < b1; j++) {
                        float4 w = ldh4(msg_in, (long)g_bt_idx[j] * HDIM + t4);
                        v[u].x -= w.x; v[u].y -= w.y; v[u].z -= w.z; v[u].w -= w.w;
                    }
                }
                uint4 st;
                st.x = f2tf(v[u].x); st.y = f2tf(v[u].y); st.z = f2tf(v[u].z); st.w = f2tf(v[u].w);
                *(uint4*)&AS(rrs[u], t4) = st;
            }
        }
    }

    float c[2][8][4];
#pragma unroll
    for (int mt = 0; mt < 2; mt++)
#pragma unroll
        for (int nt = 0; nt < 8; nt++)
#pragma unroll
            for (int r = 0; r < 4; r++) c[mt][nt][r] = 0.f;

    // preload B tile 0 from pre-converted g_Wh
    {
#pragma unroll
        for (int u = 0; u < 4; u++) {
            int idx = tid + u * 256;
            int krow = idx >> 6, cc4 = idx & 63;
            *(uint4*)&BS(krow, cc4 * 4) = *(const uint4*)&g_Wh[krow * 256 + cc4 * 4];
        }
    }
    __syncthreads();

    // ---- phase 2: GEMM over 16 k-tiles (register prefetch, single-buffer B) ----
    for (int kt = 0; kt < 16; kt++) {
        uint4 bv[4];
        if (kt < 15) {
            int k0 = (kt + 1) * 16;
#pragma unroll
            for (int u = 0; u < 4; u++) {
                int idx = tid + u * 256;
                int krow = idx >> 6, cc4 = idx & 63;
                bv[u] = *(const uint4*)&g_Wh[(k0 + krow) * 256 + cc4 * 4];
            }
        }
#pragma unroll
        for (int ks = 0; ks < 16; ks += 8) {
            unsigned a[2][4], b[8][2];
            int kbase = kt * 16 + ks;
#pragma unroll
            for (int mt = 0; mt < 2; mt++) {
                int m0 = wm + mt * 16 + gg;
                a[mt][0] = AS(m0,     kbase + tig);
                a[mt][1] = AS(m0 + 8, kbase + tig);
                a[mt][2] = AS(m0,     kbase + tig + 4);
                a[mt][3] = AS(m0 + 8, kbase + tig + 4);
            }
#pragma unroll
            for (int nt = 0; nt < 8; nt++) {
                int n0 = wn + nt * 8 + gg;
                b[nt][0] = BS(ks + tig,     n0);
                b[nt][1] = BS(ks + tig + 4, n0);
            }
#pragma unroll
            for (int mt = 0; mt < 2; mt++)
#pragma unroll
                for (int nt = 0; nt < 8; nt++)
                    mma_tf32(c[mt][nt], a[mt], b[nt]);
        }
        if (kt < 15) {
            __syncthreads();
#pragma unroll
            for (int u = 0; u < 4; u++) {
                int idx = tid + u * 256;
                int krow = idx >> 6, cc4 = idx & 63;
                *(uint4*)&BS(krow, cc4 * 4) = bv[u];
            }
            __syncthreads();
        }
    }

    // ---- epilogue: msg_out = relu(msg_input + acc), stored fp16 ----
#pragma unroll
    for (int mt = 0; mt < 2; mt++) {
#pragma unroll
        for (int nt = 0; nt < 8; nt++) {
            int col = wn + nt * 8 + tig * 2;
            long r0 = row0 + wm + mt * 16 + gg;
            if (r0 < E) {
                float2 mi = *(const float2*)&g_msg_input[r0 * 256 + col];
                float2 o;
                o.x = fmaxf(mi.x + c[mt][nt][0], 0.f);
                o.y = fmaxf(mi.y + c[mt][nt][1], 0.f);
                msg_out[(r0 * 256 + col) >> 1] = f2h(o);
            }
            long r1 = r0 + 8;
            if (r1 < E) {
                float2 mi = *(const float2*)&g_msg_input[r1 * 256 + col];
                float2 o;
                o.x = fmaxf(mi.x + c[mt][nt][2], 0.f);
                o.y = fmaxf(mi.y + c[mt][nt][3], 0.f);
                msg_out[(r1 * 256 + col) >> 1] = f2h(o);
            }
        }
    }
}

// ---------------- tf32 GEMM kernels (edge input, output) ----------------
#define APAD 20
#define BPAD 264

__global__ __launch_bounds__(256)
void k_edge_tf32(const float* __restrict__ x_nodes, const float* __restrict__ x_edges,
                 const float* __restrict__ W_i, const int* __restrict__ esrc, int E) {
    __shared__ unsigned As[2][64][APAD];
    __shared__ unsigned Bs[2][16][BPAD];
    int tid = threadIdx.x;
    int lane = tid & 31, wid = tid >> 5;
    int gg = lane >> 2, tig = lane & 3;
    int wm = (wid & 1) * 32, wn = (wid >> 1) * 64;
    long row0 = (long)blockIdx.x * 64;

    float c[2][8][4];
#pragma unroll
    for (int mt = 0; mt < 2; mt++)
#pragma unroll
        for (int nt = 0; nt < 8; nt++)
#pragma unroll
            for (int r = 0; r < 4; r++) c[mt][nt][r] = 0.f;

    const int NT = 3;
    {
#pragma unroll
        for (int u = 0; u < 4; u++) {
            int i = tid + u * 256;
            int row = i >> 4, kk = i & 15;
            long r = row0 + row;
            float v = 0.f;
            if (r < E && kk < 40)
                v = (kk < 35) ? x_nodes[(long)esrc[r] * 35 + kk] : x_edges[r * 5 + (kk - 35)];
            As[0][row][kk] = f2tf(v);
        }
#pragma unroll
        for (int u = 0; u < 4; u++) {
            int ff = tid + u * 256, krow = ff >> 6, cc = ff & 63;
            float4 bvv = make_float4(0, 0, 0, 0);
            if (krow < 40) bvv = *(const float4*)&W_i[krow * 256 + cc * 4];
            unsigned* q = &Bs[0][krow][cc * 4];
            q[0] = f2tf(bvv.x); q[1] = f2tf(bvv.y); q[2] = f2tf(bvv.z); q[3] = f2tf(bvv.w);
        }
    }
    __syncthreads();

    for (int kt = 0; kt < NT; kt++) {
        int cbuf = kt & 1, nbuf = cbuf ^ 1;
        float avs[4]; float4 bv[4];
        if (kt < NT - 1) {
            int k0 = (kt + 1) * 16;
#pragma unroll
            for (int u = 0; u < 4; u++) {
                int i = tid + u * 256;
                int row = i >> 4, kk = i & 15;
                long r = row0 + row; int gk = k0 + kk;
                float v = 0.f;
                if (r < E && gk < 40)
                    v = (gk < 35) ? x_nodes[(long)esrc[r] * 35 + gk] : x_edges[r * 5 + (gk - 35)];
                avs[u] = v;
            }
#pragma unroll
            for (int u = 0; u < 4; u++) {
                int ff = tid + u * 256, krow = ff >> 6, cc = ff & 63;
                int gk = k0 + krow;
                bv[u] = make_float4(0, 0, 0, 0);
                if (gk < 40) bv[u] = *(const float4*)&W_i[gk * 256 + cc * 4];
            }
        }
#pragma unroll
        for (int ks = 0; ks < 16; ks += 8) {
            unsigned a[2][4], b[8][2];
#pragma unroll
            for (int mt = 0; mt < 2; mt++) {
                int m0 = wm + mt * 16 + gg;
                a[mt][0] = As[cbuf][m0][ks + tig];
                a[mt][1] = As[cbuf][m0 + 8][ks + tig];
                a[mt][2] = As[cbuf][m0][ks + tig + 4];
                a[mt][3] = As[cbuf][m0 + 8][ks + tig + 4];
            }
#pragma unroll
            for (int nt = 0; nt < 8; nt++) {
                int n0 = wn + nt * 8 + gg;
                b[nt][0] = Bs[cbuf][ks + tig][n0];
                b[nt][1] = Bs[cbuf][ks + tig + 4][n0];
            }
#pragma unroll
            for (int mt = 0; mt < 2; mt++)
#pragma unroll
                for (int nt = 0; nt < 8; nt++)
                    mma_tf32(c[mt][nt], a[mt], b[nt]);
        }
        if (kt < NT - 1) {
#pragma unroll
            for (int u = 0; u < 4; u++) {
                int i = tid + u * 256;
                int row = i >> 4, kk = i & 15;
                As[nbuf][row][kk] = f2tf(avs[u]);
            }
#pragma unroll
            for (int u = 0; u < 4; u++) {
                int ff = tid + u * 256, krow = ff >> 6, cc = ff & 63;
                unsigned* q = &Bs[nbuf][krow][cc * 4];
                q[0] = f2tf(bv[u].x); q[1] = f2tf(bv[u].y); q[2] = f2tf(bv[u].z); q[3] = f2tf(bv[u].w);
            }
        }
        __syncthreads();
    }

#pragma unroll
    for (int mt = 0; mt < 2; mt++) {
#pragma unroll
        for (int nt = 0; nt < 8; nt++) {
            int col = wn + nt * 8 + tig * 2;
            long r0 = row0 + wm + mt * 16 + gg;
            if (r0 < E) {
                float2 v = make_float2(c[mt][nt][0], c[mt][nt][1]);
                *(float2*)&g_msg_input[r0 * 256 + col] = v;
                g_msgA[(r0 * 256 + col) >> 1] = f2h(make_float2(fmaxf(v.x, 0.f), fmaxf(v.y, 0.f)));
            }
            long r1 = r0 + 8;
            if (r1 < E) {
                float2 v = make_float2(c[mt][nt][2], c[mt][nt][3]);
                *(float2*)&g_msg_input[r1 * 256 + col] = v;
                g_msgA[(r1 * 256 + col) >> 1] = f2h(make_float2(fmaxf(v.x, 0.f), fmaxf(v.y, 0.f)));
            }
        }
    }
}

__global__ __launch_bounds__(256)
void k_out_tf32(const float* __restrict__ x_nodes, const float* __restrict__ W_o,
                const float* __restrict__ b_o, int N) {
    __shared__ unsigned As[2][64][APAD];
    __shared__ unsigned Bs[2][16][BPAD];
    int tid = threadIdx.x;
    int lane = tid & 31, wid = tid >> 5;
    int gg = lane >> 2, tig = lane & 3;
    int wm = (wid & 1) * 32, wn = (wid >> 1) * 64;
    long row0 = (long)blockIdx.x * 64;

    float c[2][8][4];
#pragma unroll
    for (int mt = 0; mt < 2; mt++)
#pragma unroll
        for (int nt = 0; nt < 8; nt++)
#pragma unroll
            for (int r = 0; r < 4; r++) c[mt][nt][r] = 0.f;

    const int NT = 19;
    {
#pragma unroll
        for (int u = 0; u < 4; u++) {
            int i = tid + u * 256;
            int row = i >> 4, kk = i & 15;
            long r = row0 + row;
            float v = 0.f;
            if (r < N && kk < 291)
                v = (kk < 35) ? x_nodes[r * 35 + kk] : g_m[r * 256 + (kk - 35)];
            As[0][row][kk] = f2tf(v);
        }
#pragma unroll
        for (int u = 0; u < 4; u++) {
            int ff = tid + u * 256, krow = ff >> 6, cc = ff & 63;
            float4 bvv = make_float4(0, 0, 0, 0);
            if (krow < 291) bvv = *(const float4*)&W_o[krow * 256 + cc * 4];
            unsigned* q = &Bs[0][krow][cc * 4];
            q[0] = f2tf(bvv.x); q[1] = f2tf(bvv.y); q[2] = f2tf(bvv.z); q[3] = f2tf(bvv.w);
        }
    }
    __syncthreads();

    for (int kt = 0; kt < NT; kt++) {
        int cbuf = kt & 1, nbuf = cbuf ^ 1;
        float avs[4]; float4 bv[4];
        if (kt < NT - 1) {
            int k0 = (kt + 1) * 16;
#pragma unroll
            for (int u = 0; u < 4; u++) {
                int i = tid + u * 256;
                int row = i >> 4, kk = i & 15;
                long r = row0 + row; int gk = k0 + kk;
                float v = 0.f;
                if (r < N && gk < 291)
                    v = (gk < 35) ? x_nodes[r * 35 + gk] : g_m[r * 256 + (gk - 35)];
                avs[u] = v;
            }
#pragma unroll
            for (int u = 0; u < 4; u++) {
                int ff = tid + u * 256, krow = ff >> 6, cc = ff & 63;
                int gk = k0 + krow;
                bv[u] = make_float4(0, 0, 0, 0);
                if (gk < 291) bv[u] = *(const float4*)&W_o[gk * 256 + cc * 4];
            }
        }
#pragma unroll
        for (int ks = 0; ks < 16; ks += 8) {
            unsigned a[2][4], b[8][2];
#pragma unroll
            for (int mt = 0; mt < 2; mt++) {
                int m0 = wm + mt * 16 + gg;
                a[mt][0] = As[cbuf][m0][ks + tig];
                a[mt][1] = As[cbuf][m0 + 8][ks + tig];
                a[mt][2] = As[cbuf][m0][ks + tig + 4];
                a[mt][3] = As[cbuf][m0 + 8][ks + tig + 4];
            }
#pragma unroll
            for (int nt = 0; nt < 8; nt++) {
                int n0 = wn + nt * 8 + gg;
                b[nt][0] = Bs[cbuf][ks + tig][n0];
                b[nt][1] = Bs[cbuf][ks + tig + 4][n0];
            }
#pragma unroll
            for (int mt = 0; mt < 2; mt++)
#pragma unroll
                for (int nt = 0; nt < 8; nt++)
                    mma_tf32(c[mt][nt], a[mt], b[nt]);
        }
        if (kt < NT - 1) {
#pragma unroll
            for (int u = 0; u < 4; u++) {
                int i = tid + u * 256;
                int row = i >> 4, kk = i & 15;
                As[nbuf][row][kk] = f2tf(avs[u]);
            }
#pragma unroll
            for (int u = 0; u < 4; u++) {
                int ff = tid + u * 256, krow = ff >> 6, cc = ff & 63;
                unsigned* q = &Bs[nbuf][krow][cc * 4];
                q[0] = f2tf(bv[u].x); q[1] = f2tf(bv[u].y); q[2] = f2tf(bv[u].z); q[3] = f2tf(bv[u].w);
            }
        }
        __syncthreads();
    }

#pragma unroll
    for (int mt = 0; mt < 2; mt++) {
#pragma unroll
        for (int nt = 0; nt < 8; nt++) {
            int col = wn + nt * 8 + tig * 2;
            float b0v = b_o[col], b1v = b_o[col + 1];
            long r0 = row0 + wm + mt * 16 + gg;
            if (r0 < N) {
                float2 o;
                o.x = fmaxf(c[mt][nt][0] + b0v, 0.f);
                o.y = fmaxf(c[mt][nt][1] + b1v, 0.f);
                *(float2*)&g_h[r0 * 256 + col] = o;
            }
            long r1 = r0 + 8;
            if (r1 < N) {
                float2 o;
                o.x = fmaxf(c[mt][nt][2] + b0v, 0.f);
                o.y = fmaxf(c[mt][nt][3] + b1v, 0.f);
                *(float2*)&g_h[r1 * 256 + col] = o;
            }
        }
    }
}

// per-graph mean over sorted graph_ids
__global__ void k_mean(const int* __restrict__ gid, float* __restrict__ out, int N) {
    int g = blockIdx.x;
    int t = threadIdx.x;
    int lo = 0, hi = N;
    while (lo < hi) { int m = (lo + hi) >> 1; if (gid[m] < g) lo = m + 1; else hi = m; }
    int s = lo;
    hi = N;
    while (lo < hi) { int m = (lo + hi) >> 1; if (gid[m] < g + 1) lo = m + 1; else hi = m; }
    int e = lo;
    float sum = 0.f;
    for (int n = s; n < e; n++) sum += g_h[n * HDIM + t];
    float c = (float)((e - s) > 0 ? (e - s) : 1);
    out[g * HDIM + t] = sum / c;
}

// ---------------- launcher ----------------
extern "C" void kernel_launch(void* const* d_in, const int* in_sizes, int n_in,
                              void* d_out, int out_size) {
    const float* x_nodes = (const float*)d_in[0];
    const float* x_edges = (const float*)d_in[1];
    const float* tree_m  = (const float*)d_in[2];
    const float* W_i     = (const float*)d_in[3];
    const float* W_h     = (const float*)d_in[4];
    const float* W_o     = (const float*)d_in[5];
    const float* b_o     = (const float*)d_in[6];
    const int*   esrc    = (const int*)d_in[7];
    const int*   edst    = (const int*)d_in[8];
    const int*   tgt     = (const int*)d_in[11];
    const int*   teid    = (const int*)d_in[12];
    const int*   gid     = (const int*)d_in[13];

    int N = in_sizes[0] / 35;
    int E = in_sizes[1] / 5;
    int K = in_sizes[11];
    int G = out_size / HDIM;
    float* out = (float*)d_out;

    int* d_node_ptr; cudaGetSymbolAddress((void**)&d_node_ptr, g_node_ptr);
    int* d_bt_ptr;   cudaGetSymbolAddress((void**)&d_bt_ptr, g_bt_ptr);

    cudaFuncSetAttribute(k_bp_fused, cudaFuncAttributeMaxDynamicSharedMemorySize, BP_SMEM);

    // node in-edge CSR
    k_zero_cnt<<<(N + 255) / 256, 256>>>(N);
    k_count<<<(E + 255) / 256, 256>>>(edst, E);
    k_scan<<<1, 1024>>>(d_node_ptr, N, 1);
    k_place<<<(E + 255) / 256, 256>>>(edst, E);
    // backtrack CSR
    k_bt_count<<<(E + 255) / 256, 256>>>(esrc, edst, E);
    k_scan<<<1, 1024>>>(d_bt_ptr, E, 0);
    k_bt_fill<<<(E + 255) / 256, 256>>>(esrc, edst, E);

    k_convW<<<(HDIM * HDIM + 255) / 256, 256>>>(W_h);
    k_zero_alpha<<<(N * HDIM + 255) / 256, 256>>>(N * HDIM);
    k_edge_tf32<<<(E + 63) / 64, 256>>>(x_nodes, x_edges, W_i, esrc, E);
    k_scatter_alpha<<<(K * 256 + 255) / 256, 256>>>(tree_m, tgt, teid, K);

    // it0: A->B ; it1: B->A ; it2: A->B ; final m from B
    k_nodesum<<<(N + 3) / 4, 256>>>(0, 0, N);
    k_bp_fused<<<(E + 63) / 64, 256, BP_SMEM>>>(esrc, E, 0);
    k_nodesum<<<(N + 3) / 4, 256>>>(1, 0, N);
    k_bp_fused<<<(E + 63) / 64, 256, BP_SMEM>>>(esrc, E, 1);
    k_nodesum<<<(N + 3) / 4, 256>>>(0, 0, N);
    k_bp_fused<<<(E + 63) / 64, 256, BP_SMEM>>>(esrc, E, 0);
    k_nodesum<<<(N + 3) / 4, 256>>>(1, 1, N);

    k_out_tf32<<<(N + 63) / 64, 256>>>(x_nodes, W_o, b_o, N);
    k_mean<<<G, 256>>>(gid, out, N);
}